// round 12
// baseline (speedup 1.0000x reference)
#include <cuda_runtime.h>
#include <cstdint>

// Batched Kabsch RMSD — per-warp 3-stage cp.async pipelines + split butterfly.
// 2048 CTAs x 128 threads, 4 rows/CTA (finer tail granularity).
// Each warp owns a 1536B/tensor slice of every row (warp-local
// producer/consumer -> __syncwarp only). 3 smem stages with wait_group<2>:
// a row has ~2 compute bodies (>600 cyc) of slack before consumption.
// Reduction: value-spreading butterfly (36 SHFL + 36 FADD + 19 SEL).

constexpr int BATCH = 8192;
constexpr int ROWF  = 1536;          // floats per row
constexpr int TPB   = 128;
constexpr int NW    = TPB / 32;
constexpr int RPB   = 4;             // rows per CTA
constexpr int GRID  = BATCH / RPB;   // 2048
constexpr int NSTG  = 3;             // pipeline stages
constexpr int WSLICE = ROWF / NW;    // 384 floats = 1536B per warp per tensor

__device__ __forceinline__ void cp_async16(uint32_t smem_addr, const void* gptr)
{
    asm volatile("cp.async.cg.shared.global [%0], [%1], 16;\n"
                 :: "r"(smem_addr), "l"(gptr));
}
__device__ __forceinline__ void cp_commit()
{
    asm volatile("cp.async.commit_group;\n" ::: "memory");
}
template <int N>
__device__ __forceinline__ void cp_wait()
{
    asm volatile("cp.async.wait_group %0;\n" :: "n"(N) : "memory");
}

__device__ __forceinline__ void accum_atom(float* acc,
                                           float sx, float sy, float sz,
                                           float dx, float dy, float dz)
{
    acc[0] += sx;  acc[1] += sy;  acc[2] += sz;
    acc[3] += dx;  acc[4] += dy;  acc[5] += dz;
    acc[6]  = fmaf(sx, dx, acc[6]);   acc[7]  = fmaf(sx, dy, acc[7]);   acc[8]  = fmaf(sx, dz, acc[8]);
    acc[9]  = fmaf(sy, dx, acc[9]);   acc[10] = fmaf(sy, dy, acc[10]);  acc[11] = fmaf(sy, dz, acc[11]);
    acc[12] = fmaf(sz, dx, acc[12]);  acc[13] = fmaf(sz, dy, acc[13]);  acc[14] = fmaf(sz, dz, acc[14]);
    acc[15] = fmaf(sx, sx, fmaf(sy, sy, fmaf(sz, sz, acc[15])));
    acc[16] = fmaf(dx, dx, fmaf(dy, dy, fmaf(dz, dz, acc[16])));
}

__device__ __forceinline__ float kabsch_finish(const float* v, int n)
{
    const float inv = 1.0f / (float)n;

    float R[3][3];
#pragma unroll
    for (int i = 0; i < 3; ++i)
#pragma unroll
        for (int j = 0; j < 3; ++j)
            R[i][j] = v[6 + 3 * i + j] - v[i] * v[3 + j] * inv;

    const float sq = v[15] + v[16]
        - (v[0] * v[0] + v[1] * v[1] + v[2] * v[2]) * inv
        - (v[3] * v[3] + v[4] * v[4] + v[5] * v[5]) * inv;

    const float detR =
          R[0][0] * (R[1][1] * R[2][2] - R[1][2] * R[2][1])
        - R[0][1] * (R[1][0] * R[2][2] - R[1][2] * R[2][0])
        + R[0][2] * (R[1][0] * R[2][1] - R[1][1] * R[2][0]);

    const float A00 = R[0][0]*R[0][0] + R[1][0]*R[1][0] + R[2][0]*R[2][0];
    const float A11 = R[0][1]*R[0][1] + R[1][1]*R[1][1] + R[2][1]*R[2][1];
    const float A22 = R[0][2]*R[0][2] + R[1][2]*R[1][2] + R[2][2]*R[2][2];
    const float A01 = R[0][0]*R[0][1] + R[1][0]*R[1][1] + R[2][0]*R[2][1];
    const float A02 = R[0][0]*R[0][2] + R[1][0]*R[1][2] + R[2][0]*R[2][2];
    const float A12 = R[0][1]*R[0][2] + R[1][1]*R[1][2] + R[2][1]*R[2][2];

    const float q  = (A00 + A11 + A22) * (1.0f / 3.0f);
    const float p1 = A01 * A01 + A02 * A02 + A12 * A12;
    const float b0 = A00 - q, b1 = A11 - q, b2 = A22 - q;
    const float p2 = b0 * b0 + b1 * b1 + b2 * b2 + 2.0f * p1;

    float e1, e2, e3;
    if (p2 <= 1e-12f) {
        e1 = e2 = e3 = q;
    } else {
        const float p   = sqrtf(p2 * (1.0f / 6.0f));
        const float ip  = 1.0f / p;
        const float B00 = b0 * ip, B11 = b1 * ip, B22 = b2 * ip;
        const float B01 = A01 * ip, B02 = A02 * ip, B12 = A12 * ip;
        float r =
            ( B00 * (B11 * B22 - B12 * B12)
            - B01 * (B01 * B22 - B12 * B02)
            + B02 * (B01 * B12 - B11 * B02) ) * 0.5f;
        r = fminf(1.0f, fmaxf(-1.0f, r));
        const float phi = acosf(r) * (1.0f / 3.0f);
        const float c1 = __cosf(phi);
        const float c3 = __cosf(phi + 2.0943951023931953f); // + 2*pi/3
        e1 = q + 2.0f * p * c1;
        e3 = q + 2.0f * p * c3;
        e2 = 3.0f * q - e1 - e3;
    }

    const float s1 = sqrtf(fmaxf(e1, 0.0f));
    const float s2 = sqrtf(fmaxf(e2, 0.0f));
    const float s3 = sqrtf(fmaxf(e3, 0.0f));

    const float dsign = (detR >= 0.0f) ? 1.0f : -1.0f;
    const float trace_opt = s1 + s2 + dsign * s3;

    const float msd = (sq - 2.0f * trace_opt) * inv;
    return sqrtf(fmaxf(msd, 0.0f));
}

__global__ __launch_bounds__(TPB) void kabsch_pipe3(
    const float* __restrict__ inp,
    const float* __restrict__ tgt,
    const int*   __restrict__ na32,
    float*       __restrict__ out)
{
    // [stage][tensor 0=src,1=dst][warp][384 floats]
    __shared__ float s_buf[NSTG][2][NW][WSLICE];
    __shared__ float s_red[RPB][NW][17];

    const int base = blockIdx.x * RPB;
    const int t    = threadIdx.x;
    const int w    = t >> 5;
    const int l    = t & 31;
    const int a0   = 4 * t;     // first atom this thread owns within a row

    const bool is64 = (__ldg(&na32[1]) == 0);   // num_atoms >= 16 always

    // ---- scatter-store bookkeeping for the split butterfly ----
    const bool b16 = (l & 16) != 0;
    const bool b8  = (l & 8)  != 0;
    const bool b4  = (l & 4)  != 0;
    const bool b2  = (l & 2)  != 0;
    int off = b16 ? 9 : 0;
    int cnt = b16 ? 8 : 9;
    if (b8) { off += 5; cnt -= 5; } else { cnt = min(cnt, 5); }
    if (b4) { off += 3; cnt -= 3; } else { cnt = min(cnt, 3); }
    if (b2) { off += 2; cnt -= 2; } else { cnt = min(cnt, 2); }

    const char* g_src = reinterpret_cast<const char*>(inp)
                      + (size_t)base * ROWF * 4 + (size_t)w * WSLICE * 4;
    const char* g_dst = reinterpret_cast<const char*>(tgt)
                      + (size_t)base * ROWF * 4 + (size_t)w * WSLICE * 4;

    uint32_t sm_s[NSTG], sm_d[NSTG];
#pragma unroll
    for (int s = 0; s < NSTG; ++s) {
        sm_s[s] = (uint32_t)__cvta_generic_to_shared(&s_buf[s][0][w][0]);
        sm_d[s] = (uint32_t)__cvta_generic_to_shared(&s_buf[s][1][w][0]);
    }

    // lane l copies 3 warp-contiguous 512B slices per tensor per row
    auto issue_row = [&](int k, int stage) {
        const size_t roff = (size_t)k * ROWF * 4;
        const uint32_t ss = sm_s[stage] + l * 16;
        const uint32_t sd = sm_d[stage] + l * 16;
        const char* gs = g_src + roff + l * 16;
        const char* gd = g_dst + roff + l * 16;
#pragma unroll
        for (int j = 0; j < 3; ++j) cp_async16(ss + j * 512, gs + j * 512);
#pragma unroll
        for (int j = 0; j < 3; ++j) cp_async16(sd + j * 512, gd + j * 512);
        cp_commit();
    };

    // prologue: rows 0..2 in flight (per warp, independently)
    issue_row(0, 0);
    issue_row(1, 1);
    issue_row(2, 2);

#pragma unroll
    for (int k = 0; k < RPB; ++k) {
        // pending-group budget: rows k+1.. may stay in flight
        if      (k < RPB - 2) cp_wait<2>();
        else if (k == RPB - 2) cp_wait<1>();
        else                   cp_wait<0>();
        __syncwarp();    // warp-local producer -> consumer visibility

        const int stage = k % NSTG;
        const float* bs = &s_buf[stage][0][w][12 * l];   // atoms 4t..4t+3
        const float* bd = &s_buf[stage][1][w][12 * l];
        const float4 s0 = *reinterpret_cast<const float4*>(bs + 0);
        const float4 s1 = *reinterpret_cast<const float4*>(bs + 4);
        const float4 s2 = *reinterpret_cast<const float4*>(bs + 8);
        const float4 d0 = *reinterpret_cast<const float4*>(bd + 0);
        const float4 d1 = *reinterpret_cast<const float4*>(bd + 4);
        const float4 d2 = *reinterpret_cast<const float4*>(bd + 8);

        const int row = base + k;
        const int n = is64 ? __ldg(&na32[2 * row]) : __ldg(&na32[row]);

        float acc[17];
#pragma unroll
        for (int i = 0; i < 17; ++i) acc[i] = 0.0f;

        if (a0 + 0 < n) accum_atom(acc, s0.x, s0.y, s0.z, d0.x, d0.y, d0.z);
        if (a0 + 1 < n) accum_atom(acc, s0.w, s1.x, s1.y, d0.w, d1.x, d1.y);
        if (a0 + 2 < n) accum_atom(acc, s1.z, s1.w, s2.x, d1.z, d1.w, d2.x);
        if (a0 + 3 < n) accum_atom(acc, s2.y, s2.z, s2.w, d2.y, d2.z, d2.w);

        // stage reads complete warp-wide -> refill NOW so the next rows'
        // global latency overlaps the butterfly below
        __syncwarp();
        if (k + NSTG < RPB) issue_row(k + NSTG, stage);

        // ---- split butterfly: 36 SHFL + 36 FADD + 19 SEL ----
#pragma unroll
        for (int i = 0; i < 17; ++i)
            acc[i] += __shfl_xor_sync(0xffffffffu, acc[i], 16);

        float r2[9];
#pragma unroll
        for (int j = 0; j < 9; ++j)
            r2[j] = b16 ? (j < 8 ? acc[9 + j] : 0.0f) : acc[j];
#pragma unroll
        for (int j = 0; j < 9; ++j)
            r2[j] += __shfl_xor_sync(0xffffffffu, r2[j], 8);

        float r3[5];
#pragma unroll
        for (int j = 0; j < 5; ++j)
            r3[j] = b8 ? (j < 4 ? r2[5 + j] : 0.0f) : r2[j];
#pragma unroll
        for (int j = 0; j < 5; ++j)
            r3[j] += __shfl_xor_sync(0xffffffffu, r3[j], 4);

        float r4[3];
#pragma unroll
        for (int j = 0; j < 3; ++j)
            r4[j] = b4 ? (j < 2 ? r3[3 + j] : 0.0f) : r3[j];
#pragma unroll
        for (int j = 0; j < 3; ++j)
            r4[j] += __shfl_xor_sync(0xffffffffu, r4[j], 2);

        float r5[2];
        r5[0] = b2 ? r4[2] : r4[0];
        r5[1] = b2 ? 0.0f  : r4[1];
        r5[0] += __shfl_xor_sync(0xffffffffu, r5[0], 1);
        r5[1] += __shfl_xor_sync(0xffffffffu, r5[1], 1);

        if (cnt >= 1) s_red[k][w][off]     = r5[0];
        if (cnt >= 2) s_red[k][w][off + 1] = r5[1];
    }

    __syncthreads();     // s_red complete across warps

    // ---- RPB parallel epilogues on threads 0..RPB-1 ----
    if (t < RPB) {
        float v[17];
#pragma unroll
        for (int i = 0; i < 17; ++i)
            v[i] = s_red[t][0][i] + s_red[t][1][i] + s_red[t][2][i] + s_red[t][3][i];
        const int row = base + t;
        const int n = is64 ? __ldg(&na32[2 * row]) : __ldg(&na32[row]);
        out[row] = kabsch_finish(v, n);
    }
}

extern "C" void kernel_launch(void* const* d_in, const int* in_sizes, int n_in,
                              void* d_out, int out_size)
{
    const float* inp  = (const float*)d_in[0];
    const float* tgt  = (const float*)d_in[1];
    const int*   na32 = (const int*)d_in[2];
    float*       out  = (float*)d_out;

    kabsch_pipe3<<<GRID, TPB>>>(inp, tgt, na32, out);
}

// round 13
// speedup vs baseline: 1.1252x; 1.1252x over previous
#include <cuda_runtime.h>
#include <cstdint>

// Batched Kabsch RMSD — R11 geometry (proven fastest) + hoisted num_atoms.
// 1024 CTAs x 128 threads, 8 rows/CTA, per-warp 2-stage cp.async pipelines,
// split butterfly (36 SHFL + 36 FADD). num_atoms for all 8 rows is loaded
// once into smem before the pipeline, removing a dependent scalar LDG from
// every row iteration's critical path.

constexpr int BATCH = 8192;
constexpr int ROWF  = 1536;          // floats per row
constexpr int TPB   = 128;
constexpr int NW    = TPB / 32;
constexpr int RPB   = 8;             // rows per CTA
constexpr int GRID  = BATCH / RPB;   // 1024
constexpr int WSLICE = ROWF / NW;    // 384 floats = 1536B per warp per tensor

__device__ __forceinline__ void cp_async16(uint32_t smem_addr, const void* gptr)
{
    asm volatile("cp.async.cg.shared.global [%0], [%1], 16;\n"
                 :: "r"(smem_addr), "l"(gptr));
}
__device__ __forceinline__ void cp_commit()
{
    asm volatile("cp.async.commit_group;\n" ::: "memory");
}
template <int N>
__device__ __forceinline__ void cp_wait()
{
    asm volatile("cp.async.wait_group %0;\n" :: "n"(N) : "memory");
}

__device__ __forceinline__ void accum_atom(float* acc,
                                           float sx, float sy, float sz,
                                           float dx, float dy, float dz)
{
    acc[0] += sx;  acc[1] += sy;  acc[2] += sz;
    acc[3] += dx;  acc[4] += dy;  acc[5] += dz;
    acc[6]  = fmaf(sx, dx, acc[6]);   acc[7]  = fmaf(sx, dy, acc[7]);   acc[8]  = fmaf(sx, dz, acc[8]);
    acc[9]  = fmaf(sy, dx, acc[9]);   acc[10] = fmaf(sy, dy, acc[10]);  acc[11] = fmaf(sy, dz, acc[11]);
    acc[12] = fmaf(sz, dx, acc[12]);  acc[13] = fmaf(sz, dy, acc[13]);  acc[14] = fmaf(sz, dz, acc[14]);
    acc[15] = fmaf(sx, sx, fmaf(sy, sy, fmaf(sz, sz, acc[15])));
    acc[16] = fmaf(dx, dx, fmaf(dy, dy, fmaf(dz, dz, acc[16])));
}

__device__ __forceinline__ float kabsch_finish(const float* v, int n)
{
    const float inv = 1.0f / (float)n;

    float R[3][3];
#pragma unroll
    for (int i = 0; i < 3; ++i)
#pragma unroll
        for (int j = 0; j < 3; ++j)
            R[i][j] = v[6 + 3 * i + j] - v[i] * v[3 + j] * inv;

    const float sq = v[15] + v[16]
        - (v[0] * v[0] + v[1] * v[1] + v[2] * v[2]) * inv
        - (v[3] * v[3] + v[4] * v[4] + v[5] * v[5]) * inv;

    const float detR =
          R[0][0] * (R[1][1] * R[2][2] - R[1][2] * R[2][1])
        - R[0][1] * (R[1][0] * R[2][2] - R[1][2] * R[2][0])
        + R[0][2] * (R[1][0] * R[2][1] - R[1][1] * R[2][0]);

    const float A00 = R[0][0]*R[0][0] + R[1][0]*R[1][0] + R[2][0]*R[2][0];
    const float A11 = R[0][1]*R[0][1] + R[1][1]*R[1][1] + R[2][1]*R[2][1];
    const float A22 = R[0][2]*R[0][2] + R[1][2]*R[1][2] + R[2][2]*R[2][2];
    const float A01 = R[0][0]*R[0][1] + R[1][0]*R[1][1] + R[2][0]*R[2][1];
    const float A02 = R[0][0]*R[0][2] + R[1][0]*R[1][2] + R[2][0]*R[2][2];
    const float A12 = R[0][1]*R[0][2] + R[1][1]*R[1][2] + R[2][1]*R[2][2];

    const float q  = (A00 + A11 + A22) * (1.0f / 3.0f);
    const float p1 = A01 * A01 + A02 * A02 + A12 * A12;
    const float b0 = A00 - q, b1 = A11 - q, b2 = A22 - q;
    const float p2 = b0 * b0 + b1 * b1 + b2 * b2 + 2.0f * p1;

    float e1, e2, e3;
    if (p2 <= 1e-12f) {
        e1 = e2 = e3 = q;
    } else {
        const float p   = sqrtf(p2 * (1.0f / 6.0f));
        const float ip  = 1.0f / p;
        const float B00 = b0 * ip, B11 = b1 * ip, B22 = b2 * ip;
        const float B01 = A01 * ip, B02 = A02 * ip, B12 = A12 * ip;
        float r =
            ( B00 * (B11 * B22 - B12 * B12)
            - B01 * (B01 * B22 - B12 * B02)
            + B02 * (B01 * B12 - B11 * B02) ) * 0.5f;
        r = fminf(1.0f, fmaxf(-1.0f, r));
        const float phi = acosf(r) * (1.0f / 3.0f);
        const float c1 = __cosf(phi);
        const float c3 = __cosf(phi + 2.0943951023931953f); // + 2*pi/3
        e1 = q + 2.0f * p * c1;
        e3 = q + 2.0f * p * c3;
        e2 = 3.0f * q - e1 - e3;
    }

    const float s1 = sqrtf(fmaxf(e1, 0.0f));
    const float s2 = sqrtf(fmaxf(e2, 0.0f));
    const float s3 = sqrtf(fmaxf(e3, 0.0f));

    const float dsign = (detR >= 0.0f) ? 1.0f : -1.0f;
    const float trace_opt = s1 + s2 + dsign * s3;

    const float msd = (sq - 2.0f * trace_opt) * inv;
    return sqrtf(fmaxf(msd, 0.0f));
}

__global__ __launch_bounds__(TPB, 8) void kabsch_split2(
    const float* __restrict__ inp,
    const float* __restrict__ tgt,
    const int*   __restrict__ na32,
    float*       __restrict__ out)
{
    // [stage][tensor 0=src,1=dst][warp][384 floats]
    __shared__ float s_buf[2][2][NW][WSLICE];
    __shared__ float s_red[RPB][NW][17];
    __shared__ int   s_n[RPB];

    const int base = blockIdx.x * RPB;
    const int t    = threadIdx.x;
    const int w    = t >> 5;
    const int l    = t & 31;
    const int a0   = 4 * t;     // first atom this thread owns within a row

    // ---- hoist num_atoms for all 8 rows (dtype probe: word1==0 <=> int64) ----
    if (t < RPB) {
        const bool is64 = (__ldg(&na32[1]) == 0);   // values always >= 16
        s_n[t] = is64 ? __ldg(&na32[2 * (base + t)]) : __ldg(&na32[base + t]);
    }

    // ---- scatter-store bookkeeping for the split butterfly ----
    const bool b16 = (l & 16) != 0;
    const bool b8  = (l & 8)  != 0;
    const bool b4  = (l & 4)  != 0;
    const bool b2  = (l & 2)  != 0;
    int off = b16 ? 9 : 0;
    int cnt = b16 ? 8 : 9;
    if (b8) { off += 5; cnt -= 5; } else { cnt = min(cnt, 5); }
    if (b4) { off += 3; cnt -= 3; } else { cnt = min(cnt, 3); }
    if (b2) { off += 2; cnt -= 2; } else { cnt = min(cnt, 2); }

    const char* g_src = reinterpret_cast<const char*>(inp)
                      + (size_t)base * ROWF * 4 + (size_t)w * WSLICE * 4;
    const char* g_dst = reinterpret_cast<const char*>(tgt)
                      + (size_t)base * ROWF * 4 + (size_t)w * WSLICE * 4;

    const uint32_t sm_s[2] = {
        (uint32_t)__cvta_generic_to_shared(&s_buf[0][0][w][0]),
        (uint32_t)__cvta_generic_to_shared(&s_buf[1][0][w][0]) };
    const uint32_t sm_d[2] = {
        (uint32_t)__cvta_generic_to_shared(&s_buf[0][1][w][0]),
        (uint32_t)__cvta_generic_to_shared(&s_buf[1][1][w][0]) };

    // lane l copies 3 warp-contiguous 512B slices per tensor per row
    auto issue_row = [&](int k, int stage) {
        const size_t roff = (size_t)k * ROWF * 4;
        const uint32_t ss = sm_s[stage] + l * 16;
        const uint32_t sd = sm_d[stage] + l * 16;
        const char* gs = g_src + roff + l * 16;
        const char* gd = g_dst + roff + l * 16;
#pragma unroll
        for (int j = 0; j < 3; ++j) cp_async16(ss + j * 512, gs + j * 512);
#pragma unroll
        for (int j = 0; j < 3; ++j) cp_async16(sd + j * 512, gd + j * 512);
        cp_commit();
    };

    // prologue: rows 0 and 1 in flight (per warp, independently);
    // s_n loads above overlap this fill, sealed by the one barrier below.
    issue_row(0, 0);
    issue_row(1, 1);
    __syncthreads();     // s_n visible to all warps

#pragma unroll
    for (int k = 0; k < RPB; ++k) {
        if (k < RPB - 1) cp_wait<1>();
        else             cp_wait<0>();
        __syncwarp();    // warp-local producer -> consumer visibility

        const int stage = k & 1;
        const float* bs = &s_buf[stage][0][w][12 * l];   // atoms 4t..4t+3
        const float* bd = &s_buf[stage][1][w][12 * l];
        const float4 s0 = *reinterpret_cast<const float4*>(bs + 0);
        const float4 s1 = *reinterpret_cast<const float4*>(bs + 4);
        const float4 s2 = *reinterpret_cast<const float4*>(bs + 8);
        const float4 d0 = *reinterpret_cast<const float4*>(bd + 0);
        const float4 d1 = *reinterpret_cast<const float4*>(bd + 4);
        const float4 d2 = *reinterpret_cast<const float4*>(bd + 8);

        const int n = s_n[k];

        float acc[17];
#pragma unroll
        for (int i = 0; i < 17; ++i) acc[i] = 0.0f;

        if (a0 + 0 < n) accum_atom(acc, s0.x, s0.y, s0.z, d0.x, d0.y, d0.z);
        if (a0 + 1 < n) accum_atom(acc, s0.w, s1.x, s1.y, d0.w, d1.x, d1.y);
        if (a0 + 2 < n) accum_atom(acc, s1.z, s1.w, s2.x, d1.z, d1.w, d2.x);
        if (a0 + 3 < n) accum_atom(acc, s2.y, s2.z, s2.w, d2.y, d2.z, d2.w);

        // stage reads complete warp-wide -> refill NOW so the next row's
        // global latency overlaps the butterfly below
        __syncwarp();
        if (k + 2 < RPB) issue_row(k + 2, stage);

        // ---- split butterfly: 36 SHFL + 36 FADD + 19 SEL ----
#pragma unroll
        for (int i = 0; i < 17; ++i)
            acc[i] += __shfl_xor_sync(0xffffffffu, acc[i], 16);

        float r2[9];
#pragma unroll
        for (int j = 0; j < 9; ++j)
            r2[j] = b16 ? (j < 8 ? acc[9 + j] : 0.0f) : acc[j];
#pragma unroll
        for (int j = 0; j < 9; ++j)
            r2[j] += __shfl_xor_sync(0xffffffffu, r2[j], 8);

        float r3[5];
#pragma unroll
        for (int j = 0; j < 5; ++j)
            r3[j] = b8 ? (j < 4 ? r2[5 + j] : 0.0f) : r2[j];
#pragma unroll
        for (int j = 0; j < 5; ++j)
            r3[j] += __shfl_xor_sync(0xffffffffu, r3[j], 4);

        float r4[3];
#pragma unroll
        for (int j = 0; j < 3; ++j)
            r4[j] = b4 ? (j < 2 ? r3[3 + j] : 0.0f) : r3[j];
#pragma unroll
        for (int j = 0; j < 3; ++j)
            r4[j] += __shfl_xor_sync(0xffffffffu, r4[j], 2);

        float r5[2];
        r5[0] = b2 ? r4[2] : r4[0];
        r5[1] = b2 ? 0.0f  : r4[1];
        r5[0] += __shfl_xor_sync(0xffffffffu, r5[0], 1);
        r5[1] += __shfl_xor_sync(0xffffffffu, r5[1], 1);

        if (cnt >= 1) s_red[k][w][off]     = r5[0];
        if (cnt >= 2) s_red[k][w][off + 1] = r5[1];
    }

    __syncthreads();     // s_red complete across warps

    // ---- 8 parallel epilogues on threads 0..7 ----
    if (t < RPB) {
        float v[17];
#pragma unroll
        for (int i = 0; i < 17; ++i)
            v[i] = s_red[t][0][i] + s_red[t][1][i] + s_red[t][2][i] + s_red[t][3][i];
        out[base + t] = kabsch_finish(v, s_n[t]);
    }
}

extern "C" void kernel_launch(void* const* d_in, const int* in_sizes, int n_in,
                              void* d_out, int out_size)
{
    const float* inp  = (const float*)d_in[0];
    const float* tgt  = (const float*)d_in[1];
    const int*   na32 = (const int*)d_in[2];
    float*       out  = (float*)d_out;

    kabsch_split2<<<GRID, TPB>>>(inp, tgt, na32, out);
}